// round 17
// baseline (speedup 1.0000x reference)
#include <cuda_runtime.h>
#include <cuda_bf16.h>
#include <cuda_fp16.h>
#include <cstdint>

// Problem constants
#define BB 8
#define SS 2048
#define DD 768
#define HH 768
#define MT (BB*SS)        // 16384
#define K3D (3*DD)        // 2304
#define K2D (2*DD)        // 1536

typedef long long ll;

// ---------------------------------------------------------------------------
// Scratch (device globals — allocation-free rule)
// ---------------------------------------------------------------------------
__device__ __align__(16) __nv_bfloat16 g_xcat[(ll)MT * K3D];   // x  (hi,lo,hi)
__device__ __align__(16) __half        g_yp  [(ll)MT * K2D];   // y  [yh | yl]
__device__ __align__(16) __nv_bfloat16 g_wt[2][(ll)HH * K3D];  // Wq,Wk^T (hi,hi,lo)
__device__ __align__(16) __half        g_wv  [(ll)HH * K2D];   // Wv^T [Wh | Wh]
__device__ __align__(16) float         g_q   [(ll)MT * HH];    // fp32 q (gate)
__device__ __align__(16) __nv_bfloat16 g_qcat[(ll)MT * K3D];   // q (hi,lo,hi)
__device__ __align__(16) __nv_bfloat16 g_kcat[(ll)MT * K3D];   // k (hi,hi,lo)
__device__ __align__(16) __half        g_vh  [(ll)MT * HH];    // v' fp16 row-major
__device__ __align__(16) __half        g_vt  [(ll)BB * HH * SS]; // v'^T fp16
__device__ __align__(16) float         g_s   [(ll)BB * SS * SS]; // scores
__device__ __align__(16) __half        g_ph  [(ll)MT * SS];    // probs fp16

// ---------------------------------------------------------------------------
// PTX helpers
// ---------------------------------------------------------------------------
__device__ __forceinline__ uint32_t s2u(const void* p) {
    return (uint32_t)__cvta_generic_to_shared(p);
}
__device__ __forceinline__ void ldmx4(uint32_t* r, uint32_t a) {
    asm volatile("ldmatrix.sync.aligned.m8n8.x4.shared.b16 {%0,%1,%2,%3}, [%4];"
                 : "=r"(r[0]), "=r"(r[1]), "=r"(r[2]), "=r"(r[3]) : "r"(a));
}
__device__ __forceinline__ void mmabf(float* c, const uint32_t* a, const uint32_t* b) {
    asm volatile("mma.sync.aligned.m16n8k16.row.col.f32.bf16.bf16.f32 "
                 "{%0,%1,%2,%3}, {%4,%5,%6,%7}, {%8,%9}, {%0,%1,%2,%3};"
                 : "+f"(c[0]), "+f"(c[1]), "+f"(c[2]), "+f"(c[3])
                 : "r"(a[0]), "r"(a[1]), "r"(a[2]), "r"(a[3]), "r"(b[0]), "r"(b[1]));
}
__device__ __forceinline__ void mmaf16(float* c, const uint32_t* a, const uint32_t* b) {
    asm volatile("mma.sync.aligned.m16n8k16.row.col.f32.f16.f16.f32 "
                 "{%0,%1,%2,%3}, {%4,%5,%6,%7}, {%8,%9}, {%0,%1,%2,%3};"
                 : "+f"(c[0]), "+f"(c[1]), "+f"(c[2]), "+f"(c[3])
                 : "r"(a[0]), "r"(a[1]), "r"(a[2]), "r"(a[3]), "r"(b[0]), "r"(b[1]));
}
__device__ __forceinline__ void cp16(uint32_t dst, const void* src) {
    asm volatile("cp.async.cg.shared.global [%0], [%1], 16;"
                 :: "r"(dst), "l"(src) : "memory");
}
__device__ __forceinline__ void cp_commit() {
    asm volatile("cp.async.commit_group;" ::: "memory");
}

// ---------------------------------------------------------------------------
// NT GEMM template (bf16 or fp16 mma), cp.async 4-stage ring.
//   C[z][m][n] = sum_k A[z][m][k]*B[z][n][k] (+bias[n]) (*mul)
// Block tile 128(M)x256(N)x32, 8 warps (2x4), warp tile 64x64.
// Outputs (any subset): Cf fp32, Ccat bf16x3 concat (catLo 1=A-side 2=B-side),
//                       Ch fp16.
// ---------------------------------------------------------------------------
#define KPAD 40
#define A_BYTES (128 * KPAD * 2)       // 10240
#define B_BYTES (256 * KPAD * 2)       // 20480
#define STG_BYTES (A_BYTES + B_BYTES)  // 30720
#define NSTAGE 4
#define GEMM_SMEM (NSTAGE * STG_BYTES) // 122880

__device__ __forceinline__ void issue_stage(const uint16_t* Ag, const uint16_t* Bg,
                                            int K, int kt, uint32_t sA,
                                            int lr, int lc)
{
    const ll k0 = (ll)kt * 32;
    const uint32_t sB = sA + A_BYTES;
    cp16(sA + lr * (KPAD * 2) + lc * 2,          Ag + (ll)lr * K + k0 + lc);
    cp16(sA + (lr + 64) * (KPAD * 2) + lc * 2,   Ag + (ll)(lr + 64) * K + k0 + lc);
    #pragma unroll
    for (int r = 0; r < 4; r++)
        cp16(sB + (lr + 64 * r) * (KPAD * 2) + lc * 2,
             Bg + (ll)(lr + 64 * r) * K + k0 + lc);
    cp_commit();
}

template<int FP16>
__global__ __launch_bounds__(256, 1)
void gemm_nt(const uint16_t* __restrict__ A, ll sAz,
             const uint16_t* __restrict__ B, ll sBz,
             float* __restrict__ Cf, __nv_bfloat16* __restrict__ Ccat,
             __half* __restrict__ Ch, ll sCz,
             const float* __restrict__ bias,
             const float* __restrict__ mul,
             int N, int K, int catLo)
{
    extern __shared__ char dyn[];
    const uint32_t sbase = s2u(dyn);

    const int tid = threadIdx.x;
    const int bx = blockIdx.x, by = blockIdx.y, z = blockIdx.z;
    const int lane = tid & 31, wid = tid >> 5;
    const int wm = (wid >> 2) * 64;     // 0 / 64
    const int wn = (wid & 3) * 64;      // 0/64/128/192

    const uint16_t* Ag = A + (ll)z * sAz + (ll)by * 128 * K;
    const uint16_t* Bg = B + (ll)z * sBz + (ll)bx * 256 * K;

    const int lr = tid >> 2;            // 0..63
    const int lc = (tid & 3) * 8;       // 0,8,16,24

    float acc[4][8][4];
    #pragma unroll
    for (int i = 0; i < 4; i++)
        #pragma unroll
        for (int j = 0; j < 8; j++)
            #pragma unroll
            for (int q = 0; q < 4; q++)
                acc[i][j][q] = 0.0f;

    // fragment smem element offsets (per lane) — conflict-free with KPAD=40
    const int aoff = (wm + (lane & 15)) * KPAD + ((lane >> 4) * 8);
    const int bg4 = lane >> 3;
    const int boff = (wn + ((bg4 >> 1) * 8) + (lane & 7)) * KPAD + (bg4 & 1) * 8;

    const int nk = K / 32;

    issue_stage(Ag, Bg, K, 0, sbase + 0 * STG_BYTES, lr, lc);
    issue_stage(Ag, Bg, K, 1, sbase + 1 * STG_BYTES, lr, lc);
    issue_stage(Ag, Bg, K, 2, sbase + 2 * STG_BYTES, lr, lc);

    for (int kt = 0; kt < nk; kt++) {
        asm volatile("cp.async.wait_group %0;" :: "n"(2) : "memory");
        __syncthreads();
        if (kt + 3 < nk)
            issue_stage(Ag, Bg, K, kt + 3, sbase + ((kt + 3) & 3) * STG_BYTES, lr, lc);

        const uint32_t abase = sbase + (kt & 3) * STG_BYTES;
        const uint32_t bbase = abase + A_BYTES;
        #pragma unroll
        for (int ks = 0; ks < 2; ks++) {
            uint32_t af[4][4], bfr[4][4];
            #pragma unroll
            for (int mi = 0; mi < 4; mi++)
                ldmx4(af[mi], abase + 2 * (aoff + mi * 16 * KPAD + ks * 16));
            #pragma unroll
            for (int bj = 0; bj < 4; bj++)
                ldmx4(bfr[bj], bbase + 2 * (boff + bj * 16 * KPAD + ks * 16));
            #pragma unroll
            for (int mi = 0; mi < 4; mi++)
                #pragma unroll
                for (int ni = 0; ni < 8; ni++) {
                    if (FP16) mmaf16(acc[mi][ni], af[mi], &bfr[ni >> 1][(ni & 1) * 2]);
                    else      mmabf (acc[mi][ni], af[mi], &bfr[ni >> 1][(ni & 1) * 2]);
                }
        }
    }

    // --- epilogue ---
    const int gq = lane >> 2, tig = lane & 3;
    float* Cz = Cf ? (Cf + (ll)z * sCz) : nullptr;
    __half* Hz = Ch ? (Ch + (ll)z * sCz) : nullptr;
    const float* Mz = mul ? (mul + (ll)z * sCz) : nullptr;

    #pragma unroll
    for (int mi = 0; mi < 4; mi++) {
        #pragma unroll
        for (int ni = 0; ni < 8; ni++) {
            const int row = by * 128 + wm + mi * 16 + gq;
            const int col = bx * 256 + wn + ni * 8 + tig * 2;
            float v0 = acc[mi][ni][0], v1 = acc[mi][ni][1];
            float v2 = acc[mi][ni][2], v3 = acc[mi][ni][3];
            if (bias) {
                float b0 = bias[col], b1 = bias[col + 1];
                v0 += b0; v1 += b1; v2 += b0; v3 += b1;
            }
            const ll o0 = (ll)row * N + col;
            const ll o1 = o0 + 8LL * N;
            if (Mz) {
                v0 *= Mz[o0]; v1 *= Mz[o0 + 1];
                v2 *= Mz[o1]; v3 *= Mz[o1 + 1];
            }
            if (Cz) {
                float2 r01; r01.x = v0; r01.y = v1;
                float2 r23; r23.x = v2; r23.y = v3;
                *reinterpret_cast<float2*>(Cz + o0) = r01;
                *reinterpret_cast<float2*>(Cz + o1) = r23;
            }
            if (Hz) {
                __half2 h01; h01.x = __float2half_rn(v0); h01.y = __float2half_rn(v1);
                __half2 h23; h23.x = __float2half_rn(v2); h23.y = __float2half_rn(v3);
                *reinterpret_cast<__half2*>(Hz + o0) = h01;
                *reinterpret_cast<__half2*>(Hz + o1) = h23;
            }
            if (Ccat) {
                __nv_bfloat16* K0 = Ccat + (ll)row * (3LL * N) + col;
                __nv_bfloat16* K1 = Ccat + (ll)(row + 8) * (3LL * N) + col;
                __nv_bfloat16 h0 = __float2bfloat16(v0);
                __nv_bfloat16 h1 = __float2bfloat16(v1);
                __nv_bfloat16 h2 = __float2bfloat16(v2);
                __nv_bfloat16 h3 = __float2bfloat16(v3);
                __nv_bfloat16 l0 = __float2bfloat16(v0 - __bfloat162float(h0));
                __nv_bfloat16 l1 = __float2bfloat16(v1 - __bfloat162float(h1));
                __nv_bfloat16 l2 = __float2bfloat16(v2 - __bfloat162float(h2));
                __nv_bfloat16 l3 = __float2bfloat16(v3 - __bfloat162float(h3));
                __nv_bfloat162 hp0; hp0.x = h0; hp0.y = h1;
                __nv_bfloat162 hp1; hp1.x = h2; hp1.y = h3;
                __nv_bfloat162 lp0; lp0.x = l0; lp0.y = l1;
                __nv_bfloat162 lp1; lp1.x = l2; lp1.y = l3;
                *reinterpret_cast<__nv_bfloat162*>(K0) = hp0;
                *reinterpret_cast<__nv_bfloat162*>(K1) = hp1;
                *reinterpret_cast<__nv_bfloat162*>(K0 + N) = (catLo == 1) ? lp0 : hp0;
                *reinterpret_cast<__nv_bfloat162*>(K1 + N) = (catLo == 1) ? lp1 : hp1;
                *reinterpret_cast<__nv_bfloat162*>(K0 + 2 * N) = (catLo == 1) ? hp0 : lp0;
                *reinterpret_cast<__nv_bfloat162*>(K1 + 2 * N) = (catLo == 1) ? hp1 : lp1;
            }
        }
    }
}

// ---------------------------------------------------------------------------
// fp32 -> bf16x3 split (A-side: hi,lo,hi), src [R,C] -> dst [R,3C]
// ---------------------------------------------------------------------------
__global__ void cat_split(const float* __restrict__ src, __nv_bfloat16* __restrict__ dst,
                          int C)
{
    const ll r = blockIdx.y;
    const int c = blockIdx.x * 256 + threadIdx.x;
    float x = src[r * C + c];
    __nv_bfloat16 hi = __float2bfloat16(x);
    __nv_bfloat16 lo = __float2bfloat16(x - __bfloat162float(hi));
    __nv_bfloat16* d = dst + r * (3LL * C);
    d[c] = hi;
    d[C + c] = lo;
    d[2LL * C + c] = hi;
}

// ---------------------------------------------------------------------------
// Transposed bf16x3 split (B-side: hi,hi,lo): src [P,Q] fp32 -> dst [Q,3P]
// ---------------------------------------------------------------------------
__global__ void cat_split_t(const float* __restrict__ src, __nv_bfloat16* __restrict__ dst,
                            int P, int Q)
{
    __shared__ float t[32][33];
    const int c0 = blockIdx.x * 32, r0 = blockIdx.y * 32;
    const int tx = threadIdx.x, ty = threadIdx.y;

    #pragma unroll
    for (int i = 0; i < 4; i++)
        t[ty + 8 * i][tx] = src[(ll)(r0 + ty + 8 * i) * Q + c0 + tx];
    __syncthreads();
    #pragma unroll
    for (int i = 0; i < 4; i++) {
        float x = t[tx][ty + 8 * i];
        __nv_bfloat16 hi = __float2bfloat16(x);
        __nv_bfloat16 lo = __float2bfloat16(x - __bfloat162float(hi));
        __nv_bfloat16* dr = dst + (ll)(c0 + ty + 8 * i) * (3LL * P);
        dr[r0 + tx] = hi;
        dr[P + r0 + tx] = hi;
        dr[2LL * P + r0 + tx] = lo;
    }
}

// ---------------------------------------------------------------------------
// y fp32 [R,C] -> fp16 pair [R,2C]: [yh | yl]
// ---------------------------------------------------------------------------
__global__ void pack_y(const float* __restrict__ src, __half* __restrict__ dst, int C)
{
    const ll r = blockIdx.y;
    const int c = blockIdx.x * 256 + threadIdx.x;
    float a = src[r * C + c];
    __half h = __float2half_rn(a);
    __half l = __float2half_rn(a - __half2float(h));
    __half* d = dst + r * (2LL * C);
    d[c] = h;
    d[C + c] = l;
}

// ---------------------------------------------------------------------------
// Wv fp32 [P,Q] -> Wv^T fp16 [Q,2P]: [Wh | Wh]
// ---------------------------------------------------------------------------
__global__ void pack_wv(const float* __restrict__ src, __half* __restrict__ dst,
                        int P, int Q)
{
    __shared__ float t[32][33];
    const int c0 = blockIdx.x * 32, r0 = blockIdx.y * 32;
    const int tx = threadIdx.x, ty = threadIdx.y;

    #pragma unroll
    for (int i = 0; i < 4; i++)
        t[ty + 8 * i][tx] = src[(ll)(r0 + ty + 8 * i) * Q + c0 + tx];
    __syncthreads();
    #pragma unroll
    for (int i = 0; i < 4; i++) {
        __half h = __float2half_rn(t[tx][ty + 8 * i]);
        __half* dr = dst + (ll)(c0 + ty + 8 * i) * (2LL * P);
        dr[r0 + tx] = h;
        dr[P + r0 + tx] = h;
    }
}

// ---------------------------------------------------------------------------
// fp16 transpose: vh [z*SS + s][h] -> vt [z][h][s]
// ---------------------------------------------------------------------------
__global__ void transpose_h(const __half* __restrict__ src, __half* __restrict__ dst)
{
    __shared__ __half t[32][33];
    const int z = blockIdx.z;
    const int h0 = blockIdx.x * 32, s0 = blockIdx.y * 32;
    const int tx = threadIdx.x, ty = threadIdx.y;
    const __half* s = src + (ll)z * SS * HH;
    __half* d = dst + (ll)z * HH * SS;

    #pragma unroll
    for (int i = 0; i < 4; i++)
        t[ty + 8 * i][tx] = s[(ll)(s0 + ty + 8 * i) * HH + h0 + tx];
    __syncthreads();
    #pragma unroll
    for (int i = 0; i < 4; i++)
        d[(ll)(h0 + ty + 8 * i) * SS + s0 + tx] = t[tx][ty + 8 * i];
}

// ---------------------------------------------------------------------------
// Softmax + fp16 store: scores row fp32 -> probs row fp16
// ---------------------------------------------------------------------------
__global__ void softmax_h(const float* __restrict__ S, __half* __restrict__ P)
{
    const ll row = blockIdx.x;
    const float* p = S + row * (ll)SS;
    __half* d = P + row * (ll)SS;
    const int t = threadIdx.x;
    __shared__ float red[32];

    float v[8];
    float m = -1e30f;
    #pragma unroll
    for (int i = 0; i < 8; i++) {
        v[i] = p[t + i * 256];
        m = fmaxf(m, v[i]);
    }
    #pragma unroll
    for (int o = 16; o > 0; o >>= 1) m = fmaxf(m, __shfl_xor_sync(0xffffffffu, m, o));
    if ((t & 31) == 0) red[t >> 5] = m;
    __syncthreads();
    if (t < 32) {
        float mm = (t < 8) ? red[t] : -1e30f;
        #pragma unroll
        for (int o = 16; o > 0; o >>= 1) mm = fmaxf(mm, __shfl_xor_sync(0xffffffffu, mm, o));
        if (t == 0) red[0] = mm;
    }
    __syncthreads();
    m = red[0];
    __syncthreads();

    float sum = 0.0f;
    #pragma unroll
    for (int i = 0; i < 8; i++) {
        v[i] = __expf(v[i] - m);
        sum += v[i];
    }
    #pragma unroll
    for (int o = 16; o > 0; o >>= 1) sum += __shfl_xor_sync(0xffffffffu, sum, o);
    if ((t & 31) == 0) red[t >> 5] = sum;
    __syncthreads();
    if (t < 32) {
        float ss = (t < 8) ? red[t] : 0.0f;
        #pragma unroll
        for (int o = 16; o > 0; o >>= 1) ss += __shfl_xor_sync(0xffffffffu, ss, o);
        if (t == 0) red[0] = ss;
    }
    __syncthreads();
    const float inv = 1.0f / red[0];

    #pragma unroll
    for (int i = 0; i < 8; i++)
        d[t + i * 256] = __float2half_rn(v[i] * inv);
}

// ---------------------------------------------------------------------------
extern "C" void kernel_launch(void* const* d_in, const int* in_sizes, int n_in,
                              void* d_out, int out_size)
{
    const float* x  = (const float*)d_in[0];
    const float* y  = (const float*)d_in[1];
    const float* Wq = (const float*)d_in[2];
    const float* bq = (const float*)d_in[3];
    const float* Wk = (const float*)d_in[4];
    const float* bk = (const float*)d_in[5];
    const float* Wv = (const float*)d_in[6];
    const float* bv = (const float*)d_in[7];
    float* out = (float*)d_out;

    __nv_bfloat16 *pxcat, *pwt, *pqcat, *pkcat;
    __half *pyp, *pwv, *pvh, *pvt, *pph;
    float *pq, *ps;
    cudaGetSymbolAddress((void**)&pxcat, g_xcat);
    cudaGetSymbolAddress((void**)&pyp,   g_yp);
    cudaGetSymbolAddress((void**)&pwt,   g_wt);
    cudaGetSymbolAddress((void**)&pwv,   g_wv);
    cudaGetSymbolAddress((void**)&pq,    g_q);
    cudaGetSymbolAddress((void**)&pqcat, g_qcat);
    cudaGetSymbolAddress((void**)&pkcat, g_kcat);
    cudaGetSymbolAddress((void**)&pvh,   g_vh);
    cudaGetSymbolAddress((void**)&pvt,   g_vt);
    cudaGetSymbolAddress((void**)&ps,    g_s);
    cudaGetSymbolAddress((void**)&pph,   g_ph);

    cudaFuncSetAttribute(gemm_nt<0>, cudaFuncAttributeMaxDynamicSharedMemorySize,
                         GEMM_SMEM);
    cudaFuncSetAttribute(gemm_nt<1>, cudaFuncAttributeMaxDynamicSharedMemorySize,
                         GEMM_SMEM);

    const ll wtStride = (ll)HH * K3D;

    // 1-5. pack inputs + weights
    cat_split<<<dim3(DD / 256, MT), 256>>>(x, pxcat, DD);
    pack_y<<<dim3(DD / 256, MT), 256>>>(y, pyp, DD);
    cat_split_t<<<dim3(HH / 32, DD / 32), dim3(32, 8)>>>(Wq, pwt + 0 * wtStride, DD, HH);
    cat_split_t<<<dim3(HH / 32, DD / 32), dim3(32, 8)>>>(Wk, pwt + 1 * wtStride, DD, HH);
    pack_wv<<<dim3(HH / 32, DD / 32), dim3(32, 8)>>>(Wv, pwv, DD, HH);

    // 6. Q proj (bf16x3): fp32 q (gating) + qcat (hi,lo,hi)
    dim3 gProj(HH / 256, MT / 128, 1);
    gemm_nt<0><<<gProj, 256, GEMM_SMEM>>>((const uint16_t*)pxcat, 0,
                                          (const uint16_t*)(pwt + 0 * wtStride), 0,
                                          pq, pqcat, nullptr, 0, bq, nullptr, HH, K3D, 1);
    // 7. K proj (bf16x3): kcat (hi,hi,lo)
    gemm_nt<0><<<gProj, 256, GEMM_SMEM>>>((const uint16_t*)pxcat, 0,
                                          (const uint16_t*)(pwt + 1 * wtStride), 0,
                                          nullptr, pkcat, nullptr, 0, bk, nullptr, HH, K3D, 2);
    // 8. V proj (fp16 2-product, K=1536): v' = (yWv+bv) ⊙ q -> fp16
    gemm_nt<1><<<gProj, 256, GEMM_SMEM>>>((const uint16_t*)pyp, 0,
                                          (const uint16_t*)pwv, 0,
                                          nullptr, nullptr, pvh, 0, bv, pq, HH, K2D, 0);

    // 9. scores = Q K^T (bf16x3, batched)
    dim3 gScore(SS / 256, SS / 128, BB);
    gemm_nt<0><<<gScore, 256, GEMM_SMEM>>>((const uint16_t*)pqcat, (ll)SS * K3D,
                                           (const uint16_t*)pkcat, (ll)SS * K3D,
                                           ps, nullptr, nullptr, (ll)SS * SS,
                                           nullptr, nullptr, SS, K3D, 0);

    // 10. softmax -> fp16 probs
    softmax_h<<<MT, 256>>>(ps, pph);

    // 11. v'^T (fp16 transpose per batch)
    transpose_h<<<dim3(HH / 32, SS / 32, BB), dim3(32, 8)>>>(pvh, pvt);

    // 12. context = P V' (plain fp16, K=2048)
    dim3 gCtx(HH / 256, SS / 128, BB);
    gemm_nt<1><<<gCtx, 256, GEMM_SMEM>>>((const uint16_t*)pph, (ll)SS * SS,
                                         (const uint16_t*)pvt, (ll)HH * SS,
                                         out, nullptr, nullptr, (ll)SS * HH,
                                         nullptr, nullptr, HH, SS, 0);
}